// round 2
// baseline (speedup 1.0000x reference)
#include <cuda_runtime.h>

#define B_  32
#define D_  32
#define H_  256
#define W_  256
#define K_  512
#define TILE_L 64
#define NTILES (K_ / TILE_L)          // 8
#define NTHREADS 256

// Scratch: gathered pred [B][K][D] (d contiguous, 128B per point), norms, tags.
__device__ float g_pred[B_ * K_ * D_];   // 2 MB
__device__ float g_ns[B_ * K_];
__device__ int   g_tag[B_ * K_];

__global__ void zero_out_kernel(float* out) {
    if (threadIdx.x == 0) out[0] = 0.0f;
}

// One thread per (b, k): gather 32 channels (stride H*W), precompute ||p||^2.
// kpts/tags dtype (int32 vs int64) detected from the data: if int64, the high
// dword of every value is 0 (values in [0,256)); if int32, the odd dwords are
// uniform random in [0,256) -> all-zero over 32 samples has prob 256^-32.
__global__ void gather_kernel(const float* __restrict__ ebd,
                              const void* __restrict__ kpts_raw,
                              const void* __restrict__ tags_raw) {
    int idx = blockIdx.x * blockDim.x + threadIdx.x;   // b*K + k
    if (idx >= B_ * K_) return;

    const unsigned* kd = (const unsigned*)kpts_raw;
    bool is64 = true;
#pragma unroll
    for (int i = 1; i < 64; i += 2) is64 &= (kd[i] == 0u);

    int r, c, tg;
    if (is64) {
        const long long* kp = (const long long*)kpts_raw;
        const long long* tgp = (const long long*)tags_raw;
        r  = (int)kp[(size_t)idx * 2 + 0];
        c  = (int)kp[(size_t)idx * 2 + 1];
        tg = (int)tgp[idx];
    } else {
        const int* kp = (const int*)kpts_raw;
        const int* tgp = (const int*)tags_raw;
        r  = kp[(size_t)idx * 2 + 0];
        c  = kp[(size_t)idx * 2 + 1];
        tg = tgp[idx];
    }
    // Defensive clamp: wrong dtype guess fails rel_err instead of crashing.
    r = min(max(r, 0), H_ - 1);
    c = min(max(c, 0), W_ - 1);

    int b = idx >> 9;                                  // /512
    const float* base = ebd + (size_t)b * D_ * H_ * W_ + (size_t)r * W_ + (size_t)c;
    float* dst = g_pred + (size_t)idx * D_;
    float ns = 0.0f;
#pragma unroll
    for (int d = 0; d < D_; ++d) {
        float x = base[(size_t)d * (H_ * W_)];
        dst[d] = x;
        ns += x * x;
    }
    g_ns[idx]  = ns;
    g_tag[idx] = tg;
}

// blockIdx.x = b * NTILES + tile. Block keeps the full image's pred in smem.
// Each thread owns one l (register-resident 32-vector) and 128 k rows.
extern __shared__ float smem[];

__global__ __launch_bounds__(NTHREADS) void loss_kernel(float* __restrict__ out) {
    const int b    = blockIdx.x / NTILES;
    const int tile = blockIdx.x % NTILES;

    float* pred_s = smem;                        // K*D floats = 64 KB
    float* ns_s   = smem + K_ * D_;              // K floats
    int*   tag_s  = (int*)(smem + K_ * D_ + K_); // K ints

    const int t = threadIdx.x;

    // Coalesced smem fill: 4096 float4, 16 per thread.
    {
        const float4* gp4 = (const float4*)(g_pred + (size_t)b * K_ * D_);
        float4* ps4 = (float4*)pred_s;
#pragma unroll
        for (int i = 0; i < (K_ * D_ / 4) / NTHREADS; ++i)
            ps4[t + i * NTHREADS] = gp4[t + i * NTHREADS];
        for (int i = t; i < K_; i += NTHREADS) {
            ns_s[i]  = g_ns[b * K_ + i];
            tag_s[i] = g_tag[b * K_ + i];
        }
    }
    __syncthreads();

    const int l     = tile * TILE_L + (t & (TILE_L - 1));
    const int kbase = (t / TILE_L) * (K_ / (NTHREADS / TILE_L));   // (t/64)*128

    float pl[D_];
#pragma unroll
    for (int i = 0; i < 8; ++i) {
        float4 v = ((const float4*)(pred_s + l * D_))[i];
        pl[4 * i + 0] = v.x; pl[4 * i + 1] = v.y;
        pl[4 * i + 2] = v.z; pl[4 * i + 3] = v.w;
    }
    const float nsl  = ns_s[l];
    const int   tagl = tag_s[l];

    float lsum = 0.0f;
#pragma unroll 4
    for (int k = kbase; k < kbase + 128; ++k) {
        const float4* row = (const float4*)(pred_s + k * D_);  // warp-broadcast
        float d0 = 0.f, d1 = 0.f, d2 = 0.f, d3 = 0.f;
#pragma unroll
        for (int i = 0; i < 8; ++i) {
            float4 v = row[i];
            d0 += pl[4 * i + 0] * v.x;
            d1 += pl[4 * i + 1] * v.y;
            d2 += pl[4 * i + 2] * v.z;
            d3 += pl[4 * i + 3] * v.w;
        }
        float dot  = (d0 + d1) + (d2 + d3);
        float expo = (nsl + ns_s[k] - 2.0f * dot) * (1.0f / 32.0f);
        float psim = __fdividef(2.0f, 1.0f + __expf(expo));
        float tv   = (tag_s[k] == tagl) ? 1.0f : 0.0f;
        float e    = tv - psim;
        lsum += e * e;
    }

    // Block reduction.
#pragma unroll
    for (int o = 16; o > 0; o >>= 1)
        lsum += __shfl_down_sync(0xffffffffu, lsum, o);
    __shared__ float wsum[NTHREADS / 32];
    if ((t & 31) == 0) wsum[t >> 5] = lsum;
    __syncthreads();
    if (t < NTHREADS / 32) {
        float s = wsum[t];
#pragma unroll
        for (int o = (NTHREADS / 64); o > 0; o >>= 1)
            s += __shfl_down_sync(0xffu, s, o);
        if (t == 0)
            atomicAdd(out, s * (1.0f / ((float)B_ * (float)K_ * (float)K_)));
    }
}

extern "C" void kernel_launch(void* const* d_in, const int* in_sizes, int n_in,
                              void* d_out, int out_size) {
    const float* ebd  = (const float*)d_in[0];
    const void*  kpts = (const void*)d_in[1];
    const void*  tags = (const void*)d_in[2];
    float* out = (float*)d_out;

    (void)in_sizes; (void)n_in; (void)out_size;

    size_t smem_bytes = (size_t)(K_ * D_ + K_) * sizeof(float) + (size_t)K_ * sizeof(int);
    cudaFuncSetAttribute(loss_kernel, cudaFuncAttributeMaxDynamicSharedMemorySize,
                         (int)smem_bytes);

    zero_out_kernel<<<1, 32>>>(out);
    gather_kernel<<<(B_ * K_ + NTHREADS - 1) / NTHREADS, NTHREADS>>>(ebd, kpts, tags);
    loss_kernel<<<B_ * NTILES, NTHREADS, smem_bytes>>>(out);
}

// round 3
// speedup vs baseline: 1.1660x; 1.1660x over previous
#include <cuda_runtime.h>

#define B_  32
#define D_  32
#define H_  256
#define W_  256
#define K_  512
#define TT  64                     // pair-tile size
#define NT  (K_ / TT)              // 8 tiles per image
#define NPAIRS (NT * (NT + 1) / 2) // 36 (ti <= tj)
#define NTHREADS 256

// Scratch: gathered pred [B][K][D] (d contiguous, 128B/point), norms, tags.
__device__ float g_pred[B_ * K_ * D_];   // 2 MB
__device__ float g_ns[B_ * K_];
__device__ int   g_tag[B_ * K_];

// One thread per (b, k): gather 32 channels (stride H*W), precompute ||p||^2.
// kpts/tags dtype (int32 vs int64) detected from data: int64 => high dword of
// every value is 0 (values < 256); int32 => odd dwords uniform 0..255
// (false-positive prob 256^-32). Block 0 also zeroes the output scalar.
__global__ void gather_kernel(const float* __restrict__ ebd,
                              const void* __restrict__ kpts_raw,
                              const void* __restrict__ tags_raw,
                              float* __restrict__ out) {
    if (blockIdx.x == 0 && threadIdx.x == 0) out[0] = 0.0f;

    int idx = blockIdx.x * blockDim.x + threadIdx.x;   // b*K + k
    if (idx >= B_ * K_) return;

    const unsigned* kd = (const unsigned*)kpts_raw;
    bool is64 = true;
#pragma unroll
    for (int i = 1; i < 64; i += 2) is64 &= (kd[i] == 0u);

    int r, c, tg;
    if (is64) {
        const long long* kp  = (const long long*)kpts_raw;
        const long long* tgp = (const long long*)tags_raw;
        r  = (int)kp[(size_t)idx * 2 + 0];
        c  = (int)kp[(size_t)idx * 2 + 1];
        tg = (int)tgp[idx];
    } else {
        const int* kp  = (const int*)kpts_raw;
        const int* tgp = (const int*)tags_raw;
        r  = kp[(size_t)idx * 2 + 0];
        c  = kp[(size_t)idx * 2 + 1];
        tg = tgp[idx];
    }
    r = min(max(r, 0), H_ - 1);    // defensive: fail rel_err, not a crash
    c = min(max(c, 0), W_ - 1);

    int b = idx >> 9;
    const float* base = ebd + (size_t)b * D_ * H_ * W_ + (size_t)r * W_ + (size_t)c;
    float* dst = g_pred + (size_t)idx * D_;
    float ns = 0.0f;
#pragma unroll
    for (int d = 0; d < D_; ++d) {
        float x = base[(size_t)d * (H_ * W_)];
        dst[d] = x;
        ns += x * x;
    }
    g_ns[idx]  = ns;
    g_tag[idx] = tg;
}

// Symmetry-halved pairwise loss.
// gram is symmetric and the diagonal contributes 0 (expo=0 -> psim=1=true_sim),
// so loss = sum over tile pairs (ti<=tj), weight 2 for ti<tj, 1 for ti==tj.
// blockIdx.x = b * NPAIRS + p.  Each thread: one l in tile J (registers) x 16
// k's in tile I (broadcast LDS from smem).
__global__ __launch_bounds__(NTHREADS) void loss_kernel(float* __restrict__ out) {
    const int b = blockIdx.x / NPAIRS;
    int p = blockIdx.x % NPAIRS;

    int ti = 0;
    while (p >= NT - ti) { p -= (NT - ti); ++ti; }
    const int tj = ti + p;

    __shared__ float sI[TT * D_];   // 8 KB
    __shared__ float sJ[TT * D_];   // 8 KB
    __shared__ float nsI[TT], nsJ[TT];
    __shared__ int   tgI[TT], tgJ[TT];
    __shared__ float wsum[NTHREADS / 32];

    const int t = threadIdx.x;
    const int baseI = b * K_ + ti * TT;
    const int baseJ = b * K_ + tj * TT;

    {   // coalesced tile loads: 512 float4 per tile, 2 per thread
        const float4* gI = (const float4*)(g_pred + (size_t)baseI * D_);
        const float4* gJ = (const float4*)(g_pred + (size_t)baseJ * D_);
        float4* dI = (float4*)sI;
        float4* dJ = (float4*)sJ;
#pragma unroll
        for (int i = 0; i < (TT * D_ / 4) / NTHREADS; ++i) {
            dI[t + i * NTHREADS] = gI[t + i * NTHREADS];
            dJ[t + i * NTHREADS] = gJ[t + i * NTHREADS];
        }
        if (t < TT) {
            nsI[t] = g_ns[baseI + t];
            tgI[t] = g_tag[baseI + t];
        } else if (t < 2 * TT) {
            nsJ[t - TT] = g_ns[baseJ + t - TT];
            tgJ[t - TT] = g_tag[baseJ + t - TT];
        }
    }
    __syncthreads();

    const int l     = t & (TT - 1);          // l within tile J
    const int kbase = (t >> 6) * (TT / 4);   // 16-k slice within tile I

    float pl[D_];
#pragma unroll
    for (int i = 0; i < 8; ++i) {
        float4 v = ((const float4*)(sJ + l * D_))[i];
        pl[4 * i + 0] = v.x; pl[4 * i + 1] = v.y;
        pl[4 * i + 2] = v.z; pl[4 * i + 3] = v.w;
    }
    const float nsl  = nsJ[l];
    const int   tagl = tgJ[l];

    float lsum = 0.0f;
#pragma unroll 4
    for (int kk = 0; kk < TT / 4; ++kk) {
        const int k = kbase + kk;
        const float4* row = (const float4*)(sI + k * D_);   // warp-broadcast
        float d0 = 0.f, d1 = 0.f, d2 = 0.f, d3 = 0.f;
#pragma unroll
        for (int i = 0; i < 8; ++i) {
            float4 v = row[i];
            d0 += pl[4 * i + 0] * v.x;
            d1 += pl[4 * i + 1] * v.y;
            d2 += pl[4 * i + 2] * v.z;
            d3 += pl[4 * i + 3] * v.w;
        }
        float dot  = (d0 + d1) + (d2 + d3);
        float expo = (nsl + nsI[k] - 2.0f * dot) * (1.0f / 32.0f);
        float psim = __fdividef(2.0f, 1.0f + __expf(expo));
        float tv   = (tgI[k] == tagl) ? 1.0f : 0.0f;
        float e    = tv - psim;
        lsum += e * e;
    }

    // Block reduction + weighted atomic.
#pragma unroll
    for (int o = 16; o > 0; o >>= 1)
        lsum += __shfl_down_sync(0xffffffffu, lsum, o);
    if ((t & 31) == 0) wsum[t >> 5] = lsum;
    __syncthreads();
    if (t < NTHREADS / 32) {
        float s = wsum[t];
#pragma unroll
        for (int o = (NTHREADS / 64); o > 0; o >>= 1)
            s += __shfl_down_sync(0xffu, s, o);
        if (t == 0) {
            float w = (ti == tj) ? 1.0f : 2.0f;
            atomicAdd(out, s * w * (1.0f / ((float)B_ * (float)K_ * (float)K_)));
        }
    }
}

extern "C" void kernel_launch(void* const* d_in, const int* in_sizes, int n_in,
                              void* d_out, int out_size) {
    const float* ebd  = (const float*)d_in[0];
    const void*  kpts = (const void*)d_in[1];
    const void*  tags = (const void*)d_in[2];
    float* out = (float*)d_out;

    (void)in_sizes; (void)n_in; (void)out_size;

    gather_kernel<<<(B_ * K_ + NTHREADS - 1) / NTHREADS, NTHREADS>>>(ebd, kpts, tags, out);
    loss_kernel<<<B_ * NPAIRS, NTHREADS>>>(out);
}

// round 4
// speedup vs baseline: 1.7894x; 1.5347x over previous
#include <cuda_runtime.h>

#define B_  32
#define D_  32
#define H_  256
#define W_  256
#define K_  512
#define TT  64                     // pair-tile size
#define NT  (K_ / TT)              // 8 tiles per image
#define NPAIRS (NT * (NT + 1) / 2) // 36 (ti <= tj)
#define GTHREADS 256
#define LTHREADS 128               // loss kernel: 8(k-groups) x 16(l-groups)

// Scratch: gathered pred, TRANSPOSED [B][D][K] (k contiguous), norms, tags.
__device__ float g_predT[B_ * D_ * K_];  // 2 MB
__device__ float g_ns[B_ * K_];
__device__ int   g_tag[B_ * K_];

// One thread per (b, k): gather 32 channels (stride H*W), write d-major,
// precompute ||p||^2. Stores coalesced: consecutive lanes = consecutive k.
// kpts/tags dtype (int32 vs int64) detected from data: int64 => high dword of
// every value is 0 (values < 256); false-positive prob 256^-32 for int32.
__global__ void gather_kernel(const float* __restrict__ ebd,
                              const void* __restrict__ kpts_raw,
                              const void* __restrict__ tags_raw,
                              float* __restrict__ out) {
    if (blockIdx.x == 0 && threadIdx.x == 0) out[0] = 0.0f;

    int idx = blockIdx.x * blockDim.x + threadIdx.x;   // b*K + k
    if (idx >= B_ * K_) return;

    const unsigned* kd = (const unsigned*)kpts_raw;
    bool is64 = true;
#pragma unroll
    for (int i = 1; i < 64; i += 2) is64 &= (kd[i] == 0u);

    int r, c, tg;
    if (is64) {
        const long long* kp  = (const long long*)kpts_raw;
        const long long* tgp = (const long long*)tags_raw;
        r  = (int)kp[(size_t)idx * 2 + 0];
        c  = (int)kp[(size_t)idx * 2 + 1];
        tg = (int)tgp[idx];
    } else {
        const int* kp  = (const int*)kpts_raw;
        const int* tgp = (const int*)tags_raw;
        r  = kp[(size_t)idx * 2 + 0];
        c  = kp[(size_t)idx * 2 + 1];
        tg = tgp[idx];
    }
    r = min(max(r, 0), H_ - 1);    // defensive: fail rel_err, not a crash
    c = min(max(c, 0), W_ - 1);

    int b = idx >> 9;
    int k = idx & (K_ - 1);
    const float* base = ebd + (size_t)b * D_ * H_ * W_ + (size_t)r * W_ + (size_t)c;
    float* dstT = g_predT + (size_t)b * D_ * K_ + k;
    float ns = 0.0f;
#pragma unroll
    for (int d = 0; d < D_; ++d) {
        float x = base[(size_t)d * (H_ * W_)];
        dstT[(size_t)d * K_] = x;
        ns += x * x;
    }
    g_ns[idx]  = ns;
    g_tag[idx] = tg;
}

// Symmetry-halved pairwise loss, micro-GEMM register blocking.
// blockIdx.x = b * NPAIRS + p -> tile pair (ti <= tj), off-diag weight 2.
// 128 threads: kg = t&7 (8 k-values each), lg = t>>3 (4 l-values each).
// Inner loop over d: 3x LDS.128 + 32 FFMA (FMA-bound, crossbar ~75%).
__global__ __launch_bounds__(LTHREADS) void loss_kernel(float* __restrict__ out) {
    const int b = blockIdx.x / NPAIRS;
    int p = blockIdx.x % NPAIRS;
    int ti = 0;
    while (p >= NT - ti) { p -= (NT - ti); ++ti; }
    const int tj = ti + p;

    __shared__ float sI[D_ * TT];   // [d][k] 8 KB
    __shared__ float sJ[D_ * TT];   // [d][l] 8 KB
    __shared__ float nsI[TT], nsJ[TT];
    __shared__ int   tgI[TT], tgJ[TT];
    __shared__ float wsum[LTHREADS / 32];

    const int t = threadIdx.x;
    const float* srcI = g_predT + (size_t)b * D_ * K_ + ti * TT;
    const float* srcJ = g_predT + (size_t)b * D_ * K_ + tj * TT;

    // Tile loads: 512 float4 per tile, 4 per thread. Row d occupies 16 float4.
#pragma unroll
    for (int rr = 0; rr < 4; ++rr) {
        int idx4 = t + rr * LTHREADS;      // 0..511
        int d  = idx4 >> 4;
        int j4 = idx4 & 15;
        ((float4*)sI)[idx4] = *(const float4*)(srcI + (size_t)d * K_ + j4 * 4);
        ((float4*)sJ)[idx4] = *(const float4*)(srcJ + (size_t)d * K_ + j4 * 4);
    }
    {
        const int baseI = b * K_ + ti * TT;
        const int baseJ = b * K_ + tj * TT;
        if (t < TT) {
            nsI[t] = g_ns[baseI + t];
            tgI[t] = g_tag[baseI + t];
        } else {
            nsJ[t - TT] = g_ns[baseJ + t - TT];
            tgJ[t - TT] = g_tag[baseJ + t - TT];
        }
    }
    __syncthreads();

    const int k0 = (t & 7) * 8;     // 8 k's in tile I
    const int l0 = (t >> 3) * 4;    // 4 l's in tile J

    float acc[8][4];
#pragma unroll
    for (int i = 0; i < 8; ++i)
#pragma unroll
        for (int j = 0; j < 4; ++j) acc[i][j] = 0.0f;

#pragma unroll 4
    for (int d = 0; d < D_; ++d) {
        float4 ka = *(const float4*)(sI + d * TT + k0);
        float4 kb = *(const float4*)(sI + d * TT + k0 + 4);
        float4 lv = *(const float4*)(sJ + d * TT + l0);
        float kf[8] = {ka.x, ka.y, ka.z, ka.w, kb.x, kb.y, kb.z, kb.w};
        float lf[4] = {lv.x, lv.y, lv.z, lv.w};
#pragma unroll
        for (int i = 0; i < 8; ++i)
#pragma unroll
            for (int j = 0; j < 4; ++j)
                acc[i][j] += kf[i] * lf[j];
    }

    // Epilogue: 32 pairs per thread.
    float nsk[8], nsl[4];
    int   tgk[8], tgl[4];
#pragma unroll
    for (int i = 0; i < 8; ++i) { nsk[i] = nsI[k0 + i]; tgk[i] = tgI[k0 + i]; }
#pragma unroll
    for (int j = 0; j < 4; ++j) { nsl[j] = nsJ[l0 + j]; tgl[j] = tgJ[l0 + j]; }

    float lsum = 0.0f;
#pragma unroll
    for (int i = 0; i < 8; ++i) {
#pragma unroll
        for (int j = 0; j < 4; ++j) {
            float expo = (nsk[i] + nsl[j] - 2.0f * acc[i][j]) * (1.0f / 32.0f);
            float psim = __fdividef(2.0f, 1.0f + __expf(expo));
            float tv   = (tgk[i] == tgl[j]) ? 1.0f : 0.0f;
            float e    = tv - psim;
            lsum += e * e;
        }
    }

    // Block reduction + weighted atomic.
#pragma unroll
    for (int o = 16; o > 0; o >>= 1)
        lsum += __shfl_down_sync(0xffffffffu, lsum, o);
    if ((t & 31) == 0) wsum[t >> 5] = lsum;
    __syncthreads();
    if (t < LTHREADS / 32) {
        float s = wsum[t];
#pragma unroll
        for (int o = (LTHREADS / 64); o > 0; o >>= 1)
            s += __shfl_down_sync(0xfu, s, o);
        if (t == 0) {
            float w = (ti == tj) ? 1.0f : 2.0f;
            atomicAdd(out, s * w * (1.0f / ((float)B_ * (float)K_ * (float)K_)));
        }
    }
}

extern "C" void kernel_launch(void* const* d_in, const int* in_sizes, int n_in,
                              void* d_out, int out_size) {
    const float* ebd  = (const float*)d_in[0];
    const void*  kpts = (const void*)d_in[1];
    const void*  tags = (const void*)d_in[2];
    float* out = (float*)d_out;

    (void)in_sizes; (void)n_in; (void)out_size;

    gather_kernel<<<(B_ * K_ + GTHREADS - 1) / GTHREADS, GTHREADS>>>(ebd, kpts, tags, out);
    loss_kernel<<<B_ * NPAIRS, LTHREADS>>>(out);
}

// round 5
// speedup vs baseline: 2.2137x; 1.2371x over previous
#include <cuda_runtime.h>

#define B_  32
#define D_  32
#define H_  256
#define W_  256
#define K_  512
#define TT  64                     // pair-tile size
#define NT  (K_ / TT)              // 8 tiles per image
#define NPAIRS (NT * (NT + 1) / 2) // 36 (ti <= tj)
#define GTHREADS 256
#define LTHREADS 64                // loss kernel: 8x8 thread grid, 8x8 regs each

// Scratch: gathered pred, TRANSPOSED [B][D][K] (k contiguous), norms, tags.
__device__ float g_predT[B_ * D_ * K_];  // 2 MB
__device__ float g_ns[B_ * K_];
__device__ int   g_tag[B_ * K_];

__device__ __forceinline__ float tanh_approx(float x) {
    float y;
    asm("tanh.approx.f32 %0, %1;" : "=f"(y) : "f"(x));
    return y;
}

// One thread per (b, k): gather 32 channels (stride H*W), write d-major,
// precompute ||p||^2. kpts/tags dtype (int32 vs int64) detected from data:
// int64 => high dword of every value is 0 (values < 256).
__global__ void gather_kernel(const float* __restrict__ ebd,
                              const void* __restrict__ kpts_raw,
                              const void* __restrict__ tags_raw,
                              float* __restrict__ out) {
    if (blockIdx.x == 0 && threadIdx.x == 0) out[0] = 0.0f;

    int idx = blockIdx.x * blockDim.x + threadIdx.x;   // b*K + k
    if (idx >= B_ * K_) return;

    const unsigned* kd = (const unsigned*)kpts_raw;
    bool is64 = true;
#pragma unroll
    for (int i = 1; i < 64; i += 2) is64 &= (kd[i] == 0u);

    int r, c, tg;
    if (is64) {
        const long long* kp  = (const long long*)kpts_raw;
        const long long* tgp = (const long long*)tags_raw;
        r  = (int)kp[(size_t)idx * 2 + 0];
        c  = (int)kp[(size_t)idx * 2 + 1];
        tg = (int)tgp[idx];
    } else {
        const int* kp  = (const int*)kpts_raw;
        const int* tgp = (const int*)tags_raw;
        r  = kp[(size_t)idx * 2 + 0];
        c  = kp[(size_t)idx * 2 + 1];
        tg = tgp[idx];
    }
    r = min(max(r, 0), H_ - 1);
    c = min(max(c, 0), W_ - 1);

    int b = idx >> 9;
    int k = idx & (K_ - 1);
    const float* base = ebd + (size_t)b * D_ * H_ * W_ + (size_t)r * W_ + (size_t)c;
    float* dstT = g_predT + (size_t)b * D_ * K_ + k;
    float ns = 0.0f;
#pragma unroll
    for (int d = 0; d < D_; ++d) {
        float x = base[(size_t)d * (H_ * W_)];
        dstT[(size_t)d * K_] = x;
        ns += x * x;
    }
    g_ns[idx]  = ns;
    g_tag[idx] = tg;
}

// Symmetry-halved pairwise loss, 8x8 register micro-GEMM on 64 threads.
// Thread t: k in {k0..k0+3, k0+32..k0+35} (k0=(t&7)*4),
//           l in {l0..l0+3, l0+32..l0+35} (l0=(t>>3)*4).
// All four LDS.128 per d are 16B-stride, conflict-free.
// psim = 2/(1+exp(x)) = 1 - tanh(x/2)  ->  e = tanh(arg) - neq.
__global__ __launch_bounds__(LTHREADS) void loss_kernel(float* __restrict__ out) {
    const int b = blockIdx.x / NPAIRS;
    int p = blockIdx.x % NPAIRS;
    int ti = 0;
    while (p >= NT - ti) { p -= (NT - ti); ++ti; }
    const int tj = ti + p;

    __shared__ float sI[D_ * TT];   // [d][k] 8 KB
    __shared__ float sJ[D_ * TT];   // [d][l] 8 KB
    __shared__ float nsI[TT], nsJ[TT];
    __shared__ int   tgI[TT], tgJ[TT];
    __shared__ float wsum[2];

    const int t = threadIdx.x;
    const float* srcI = g_predT + (size_t)b * D_ * K_ + ti * TT;
    const float* srcJ = g_predT + (size_t)b * D_ * K_ + tj * TT;

    // Fill: 512 float4 per tile, 8 per thread. Row d = 16 float4.
#pragma unroll
    for (int rr = 0; rr < 8; ++rr) {
        int idx4 = t + rr * LTHREADS;     // 0..511
        int d  = idx4 >> 4;
        int j4 = idx4 & 15;
        ((float4*)sI)[idx4] = *(const float4*)(srcI + (size_t)d * K_ + j4 * 4);
        ((float4*)sJ)[idx4] = *(const float4*)(srcJ + (size_t)d * K_ + j4 * 4);
    }
    {
        const int baseI = b * K_ + ti * TT;
        const int baseJ = b * K_ + tj * TT;
        nsI[t] = g_ns[baseI + t];        tgI[t] = g_tag[baseI + t];
        nsJ[t] = g_ns[baseJ + t];        tgJ[t] = g_tag[baseJ + t];
    }
    __syncthreads();

    const int k0 = (t & 7) * 4;
    const int l0 = (t >> 3) * 4;

    float acc[8][8];
#pragma unroll
    for (int i = 0; i < 8; ++i)
#pragma unroll
        for (int j = 0; j < 8; ++j) acc[i][j] = 0.0f;

    const float* pI = sI + k0;
    const float* pJ = sJ + l0;
#pragma unroll 4
    for (int d = 0; d < D_; ++d) {
        float4 a0 = *(const float4*)(pI + d * TT);
        float4 a1 = *(const float4*)(pI + d * TT + 32);
        float4 b0 = *(const float4*)(pJ + d * TT);
        float4 b1 = *(const float4*)(pJ + d * TT + 32);
        float kf[8] = {a0.x, a0.y, a0.z, a0.w, a1.x, a1.y, a1.z, a1.w};
        float lf[8] = {b0.x, b0.y, b0.z, b0.w, b1.x, b1.y, b1.z, b1.w};
#pragma unroll
        for (int i = 0; i < 8; ++i)
#pragma unroll
            for (int j = 0; j < 8; ++j)
                acc[i][j] += kf[i] * lf[j];
    }

    // Epilogue: 64 pairs. arg = (nsk + nsl - 2*dot)/64; e = tanh(arg) - neq.
    float nsk2[8], nsl2[8];
    int   tgk[8], tgl[8];
#pragma unroll
    for (int i = 0; i < 4; ++i) {
        nsk2[i]     = nsI[k0 + i]      * (1.0f / 64.0f);
        nsk2[i + 4] = nsI[k0 + 32 + i] * (1.0f / 64.0f);
        tgk[i]      = tgI[k0 + i];
        tgk[i + 4]  = tgI[k0 + 32 + i];
        nsl2[i]     = nsJ[l0 + i]      * (1.0f / 64.0f);
        nsl2[i + 4] = nsJ[l0 + 32 + i] * (1.0f / 64.0f);
        tgl[i]      = tgJ[l0 + i];
        tgl[i + 4]  = tgJ[l0 + 32 + i];
    }

    float lsum = 0.0f;
#pragma unroll
    for (int i = 0; i < 8; ++i) {
#pragma unroll
        for (int j = 0; j < 8; ++j) {
            float arg = fmaf(acc[i][j], -1.0f / 32.0f, nsk2[i] + nsl2[j]);
            float th  = tanh_approx(arg);
            float e   = th - ((tgk[i] != tgl[j]) ? 1.0f : 0.0f);
            lsum += e * e;
        }
    }

    // Block reduction (2 warps) + weighted atomic.
#pragma unroll
    for (int o = 16; o > 0; o >>= 1)
        lsum += __shfl_down_sync(0xffffffffu, lsum, o);
    if ((t & 31) == 0) wsum[t >> 5] = lsum;
    __syncthreads();
    if (t == 0) {
        float w = (ti == tj) ? 1.0f : 2.0f;
        atomicAdd(out, (wsum[0] + wsum[1]) * w *
                       (1.0f / ((float)B_ * (float)K_ * (float)K_)));
    }
}

extern "C" void kernel_launch(void* const* d_in, const int* in_sizes, int n_in,
                              void* d_out, int out_size) {
    const float* ebd  = (const float*)d_in[0];
    const void*  kpts = (const void*)d_in[1];
    const void*  tags = (const void*)d_in[2];
    float* out = (float*)d_out;

    (void)in_sizes; (void)n_in; (void)out_size;

    gather_kernel<<<(B_ * K_ + GTHREADS - 1) / GTHREADS, GTHREADS>>>(ebd, kpts, tags, out);
    loss_kernel<<<B_ * NPAIRS, LTHREADS>>>(out);
}

// round 7
// speedup vs baseline: 2.4593x; 1.1109x over previous
#include <cuda_runtime.h>

#define B_  32
#define D_  32
#define H_  256
#define W_  256
#define K_  512
#define TT  64                     // pair-tile size
#define NT  (K_ / TT)              // 8 tiles per image
#define NPAIRS (NT * (NT + 1) / 2) // 36 (ti <= tj)
#define GTHREADS 256
#define LTHREADS 64                // loss kernel: 8x8 thread grid, 8x8 regs each

typedef unsigned long long ull;

// Scratch: gathered pred, TRANSPOSED [B][D][K] (k contiguous), norms, tags.
__device__ float g_predT[B_ * D_ * K_];  // 2 MB
__device__ float g_ns[B_ * K_];
__device__ int   g_tag[B_ * K_];

__device__ __forceinline__ float tanh_approx(float x) {
    float y;
    asm("tanh.approx.f32 %0, %1;" : "=f"(y) : "f"(x));
    return y;
}
__device__ __forceinline__ ull pack2(float lo, float hi) {
    ull r;
    asm("mov.b64 %0, {%1, %2};" : "=l"(r) : "f"(lo), "f"(hi));
    return r;
}
__device__ __forceinline__ void fma2(ull& acc, ull a, ull b) {
    asm("fma.rn.f32x2 %0, %1, %2, %0;" : "+l"(acc) : "l"(a), "l"(b));
}

union F4U { float4 f; ull u[2]; };
union UF  { ull u; float f[2]; };

// Two threads per (b, k): each gathers 16 channels, writes d-major,
// partial ||p||^2 combined via shfl. dtype (int32 vs int64) detected from
// data: int64 => high dword of every value is 0 (values < 256).
__global__ void gather_kernel(const float* __restrict__ ebd,
                              const void* __restrict__ kpts_raw,
                              const void* __restrict__ tags_raw,
                              float* __restrict__ out) {
    if (blockIdx.x == 0 && threadIdx.x == 0) out[0] = 0.0f;

    int tid = blockIdx.x * blockDim.x + threadIdx.x;   // 2 * (b*K + k) + h
    if (tid >= B_ * K_ * 2) return;
    int idx = tid >> 1;            // point index b*K + k
    int h   = tid & 1;             // d-half

    const unsigned* kd = (const unsigned*)kpts_raw;
    bool is64 = true;
#pragma unroll
    for (int i = 1; i < 64; i += 2) is64 &= (__ldg(kd + i) == 0u);

    int r, c, tg;
    if (is64) {
        const long long* kp  = (const long long*)kpts_raw;
        const long long* tgp = (const long long*)tags_raw;
        r  = (int)kp[(size_t)idx * 2 + 0];
        c  = (int)kp[(size_t)idx * 2 + 1];
        tg = (int)tgp[idx];
    } else {
        const int* kp  = (const int*)kpts_raw;
        const int* tgp = (const int*)tags_raw;
        r  = kp[(size_t)idx * 2 + 0];
        c  = kp[(size_t)idx * 2 + 1];
        tg = tgp[idx];
    }
    r = min(max(r, 0), H_ - 1);
    c = min(max(c, 0), W_ - 1);

    int b = idx >> 9;
    int k = idx & (K_ - 1);
    const int d0 = h * (D_ / 2);
    const float* base = ebd + (size_t)b * D_ * H_ * W_ + (size_t)d0 * (H_ * W_)
                            + (size_t)r * W_ + (size_t)c;
    float* dstT = g_predT + (size_t)b * D_ * K_ + (size_t)d0 * K_ + k;
    float ns = 0.0f;
#pragma unroll
    for (int d = 0; d < D_ / 2; ++d) {
        float x = base[(size_t)d * (H_ * W_)];
        dstT[(size_t)d * K_] = x;
        ns += x * x;
    }
    ns += __shfl_xor_sync(0xffffffffu, ns, 1);
    if (h == 0) {
        g_ns[idx]  = ns;
        g_tag[idx] = tg;
    }
}

// Symmetry-halved pairwise loss, 8x8 register micro-GEMM on 64 threads,
// inner product via packed fma.rn.f32x2 (k-paired accumulators).
// Thread t: k in {k0..k0+3, k0+32..k0+35} (k0=(t&7)*4),
//           l in {l0..l0+3, l0+32..l0+35} (l0=(t>>3)*4).
// psim = 2/(1+exp(x)) = 1 - tanh(x/2)  ->  e = tanh(arg) - neq.
__global__ __launch_bounds__(LTHREADS) void loss_kernel(float* __restrict__ out) {
    const int b = blockIdx.x / NPAIRS;
    int p = blockIdx.x % NPAIRS;
    int ti = 0;
    while (p >= NT - ti) { p -= (NT - ti); ++ti; }
    const int tj = ti + p;

    __shared__ float sI[D_ * TT];   // [d][k] 8 KB
    __shared__ float sJ[D_ * TT];   // [d][l] 8 KB
    __shared__ float nsI[TT], nsJ[TT];
    __shared__ int   tgI[TT], tgJ[TT];
    __shared__ float wsum[2];

    const int t = threadIdx.x;
    const float* srcI = g_predT + (size_t)b * D_ * K_ + ti * TT;
    const float* srcJ = g_predT + (size_t)b * D_ * K_ + tj * TT;

    // Fill: 512 float4 per tile, 8 per thread. Row d = 16 float4.
#pragma unroll
    for (int rr = 0; rr < 8; ++rr) {
        int idx4 = t + rr * LTHREADS;     // 0..511
        int d  = idx4 >> 4;
        int j4 = idx4 & 15;
        ((float4*)sI)[idx4] = *(const float4*)(srcI + (size_t)d * K_ + j4 * 4);
        ((float4*)sJ)[idx4] = *(const float4*)(srcJ + (size_t)d * K_ + j4 * 4);
    }
    {
        const int baseI = b * K_ + ti * TT;
        const int baseJ = b * K_ + tj * TT;
        nsI[t] = g_ns[baseI + t];        tgI[t] = g_tag[baseI + t];
        nsJ[t] = g_ns[baseJ + t];        tgJ[t] = g_tag[baseJ + t];
    }
    __syncthreads();

    const int k0 = (t & 7) * 4;
    const int l0 = (t >> 3) * 4;

    // acc2[ip][j]: packed pair (k_{2ip}, k_{2ip+1}) x l_j, ip mapping:
    // ip0 -> (k0, k0+1), ip1 -> (k0+2, k0+3), ip2 -> (k0+32, k0+33),
    // ip3 -> (k0+34, k0+35). l_j: j<4 -> l0+j, j>=4 -> l0+32+(j-4).
    ull acc2[4][8];
#pragma unroll
    for (int i = 0; i < 4; ++i)
#pragma unroll
        for (int j = 0; j < 8; ++j) acc2[i][j] = 0ull;

    const float* pI = sI + k0;
    const float* pJ = sJ + l0;
#pragma unroll 4
    for (int d = 0; d < D_; ++d) {
        F4U a0, a1, b0, b1;
        a0.f = *(const float4*)(pI + d * TT);
        a1.f = *(const float4*)(pI + d * TT + 32);
        b0.f = *(const float4*)(pJ + d * TT);
        b1.f = *(const float4*)(pJ + d * TT + 32);
        ull ku[4] = {a0.u[0], a0.u[1], a1.u[0], a1.u[1]};
        ull ld[8] = {pack2(b0.f.x, b0.f.x), pack2(b0.f.y, b0.f.y),
                     pack2(b0.f.z, b0.f.z), pack2(b0.f.w, b0.f.w),
                     pack2(b1.f.x, b1.f.x), pack2(b1.f.y, b1.f.y),
                     pack2(b1.f.z, b1.f.z), pack2(b1.f.w, b1.f.w)};
#pragma unroll
        for (int i = 0; i < 4; ++i)
#pragma unroll
            for (int j = 0; j < 8; ++j)
                fma2(acc2[i][j], ku[i], ld[j]);
    }

    // Epilogue: 64 pairs. arg = (nsk + nsl - 2*dot)/64; e = tanh(arg) - neq.
    float nsk2[8], nsl2[8];
    int   tgk[8], tgl[8];
#pragma unroll
    for (int i = 0; i < 4; ++i) {
        nsk2[i]     = nsI[k0 + i]      * (1.0f / 64.0f);
        nsk2[i + 4] = nsI[k0 + 32 + i] * (1.0f / 64.0f);
        tgk[i]      = tgI[k0 + i];
        tgk[i + 4]  = tgI[k0 + 32 + i];
        nsl2[i]     = nsJ[l0 + i]      * (1.0f / 64.0f);
        nsl2[i + 4] = nsJ[l0 + 32 + i] * (1.0f / 64.0f);
        tgl[i]      = tgJ[l0 + i];
        tgl[i + 4]  = tgJ[l0 + 32 + i];
    }

    float lsum = 0.0f;
#pragma unroll
    for (int ip = 0; ip < 4; ++ip) {
#pragma unroll
        for (int j = 0; j < 8; ++j) {
            UF v; v.u = acc2[ip][j];
            int i0 = 2 * ip;          // index into nsk2/tgk mapping
            int i1 = 2 * ip + 1;
            float arg0 = fmaf(v.f[0], -1.0f / 32.0f, nsk2[i0] + nsl2[j]);
            float arg1 = fmaf(v.f[1], -1.0f / 32.0f, nsk2[i1] + nsl2[j]);
            float e0 = tanh_approx(arg0) - ((tgk[i0] != tgl[j]) ? 1.0f : 0.0f);
            float e1 = tanh_approx(arg1) - ((tgk[i1] != tgl[j]) ? 1.0f : 0.0f);
            lsum += e0 * e0 + e1 * e1;
        }
    }

    // Block reduction (2 warps) + weighted atomic.
#pragma unroll
    for (int o = 16; o > 0; o >>= 1)
        lsum += __shfl_down_sync(0xffffffffu, lsum, o);
    if ((t & 31) == 0) wsum[t >> 5] = lsum;
    __syncthreads();
    if (t == 0) {
        float w = (ti == tj) ? 1.0f : 2.0f;
        atomicAdd(out, (wsum[0] + wsum[1]) * w *
                       (1.0f / ((float)B_ * (float)K_ * (float)K_)));
    }
}

extern "C" void kernel_launch(void* const* d_in, const int* in_sizes, int n_in,
                              void* d_out, int out_size) {
    const float* ebd  = (const float*)d_in[0];
    const void*  kpts = (const void*)d_in[1];
    const void*  tags = (const void*)d_in[2];
    float* out = (float*)d_out;

    (void)in_sizes; (void)n_in; (void)out_size;

    gather_kernel<<<(B_ * K_ * 2 + GTHREADS - 1) / GTHREADS, GTHREADS>>>(ebd, kpts, tags, out);
    loss_kernel<<<B_ * NPAIRS, LTHREADS>>>(out);
}